// round 4
// baseline (speedup 1.0000x reference)
#include <cuda_runtime.h>

#define B_  32
#define N_  512
#define M_  512
#define D_  64
#define BIGF 1e10f

// Scratch (static device arrays — no allocation allowed)
__device__ float g_D [B_ * N_ * M_];   // 32 MB distance matrices, row-major [b][i][j]
__device__ float g_x2[B_ * N_];
__device__ float g_y2[B_ * M_];

// ---------------------------------------------------------------------------
// Kernel 1: row norms |x_i|^2 and |y_j|^2
// ---------------------------------------------------------------------------
__global__ __launch_bounds__(256) void norm_kernel(const float* __restrict__ x,
                                                   const float* __restrict__ y) {
    int t = blockIdx.x * blockDim.x + threadIdx.x;   // 0 .. 2*B_*512-1
    const int total = B_ * N_;
    const float* src;
    float* dst;
    int r;
    if (t < total) { src = x; dst = g_x2; r = t; }
    else           { src = y; dst = g_y2; r = t - total; }
    const float4* p = (const float4*)(src + (size_t)r * D_);
    float s = 0.f;
#pragma unroll
    for (int i = 0; i < D_ / 4; ++i) {
        float4 v = p[i];
        s = fmaf(v.x, v.x, s);
        s = fmaf(v.y, v.y, s);
        s = fmaf(v.z, v.z, s);
        s = fmaf(v.w, v.w, s);
    }
    dst[r] = s;
}

// ---------------------------------------------------------------------------
// Kernel 2: distance tiles  D = x2 + y2 - 2 * (X @ Y^T)
// 64x64 tile, 256 threads, 4x4 micro-tile, K=64 in one pass.
// Smem stored transposed [k][row] (stride SP=68 -> 16B-aligned float4 reads,
// conflict-free because lanes store consecutive rows).
// ---------------------------------------------------------------------------
#define TS 64
#define SP 68

__global__ __launch_bounds__(256) void dist_kernel(const float* __restrict__ x,
                                                   const float* __restrict__ y) {
    __shared__ float Xs[D_ * SP];
    __shared__ float Ys[D_ * SP];

    const int b  = blockIdx.z;
    const int i0 = blockIdx.y * TS;
    const int j0 = blockIdx.x * TS;
    const float* xb = x + ((size_t)b * N_ + i0) * D_;
    const float* yb = y + ((size_t)b * M_ + j0) * D_;
    const int tid = threadIdx.x;

    // Load 64 rows x 64 dims of each matrix, transposed into smem.
    // f = float4 index; lane-consecutive rows -> conflict-free STS.
#pragma unroll
    for (int it = 0; it < 4; ++it) {
        int f   = tid + it * 256;
        int row = f & 63;
        int c4  = f >> 6;            // 0..15
        float4 vx = *(const float4*)(xb + row * D_ + c4 * 4);
        float4 vy = *(const float4*)(yb + row * D_ + c4 * 4);
        Xs[(c4 * 4 + 0) * SP + row] = vx.x;
        Xs[(c4 * 4 + 1) * SP + row] = vx.y;
        Xs[(c4 * 4 + 2) * SP + row] = vx.z;
        Xs[(c4 * 4 + 3) * SP + row] = vx.w;
        Ys[(c4 * 4 + 0) * SP + row] = vy.x;
        Ys[(c4 * 4 + 1) * SP + row] = vy.y;
        Ys[(c4 * 4 + 2) * SP + row] = vy.z;
        Ys[(c4 * 4 + 3) * SP + row] = vy.w;
    }
    __syncthreads();

    const int tx = tid & 15, ty = tid >> 4;
    const int ia = ty * 4, ja = tx * 4;

    float acc[4][4] = {};
#pragma unroll
    for (int k = 0; k < D_; ++k) {
        float4 a  = *(const float4*)&Xs[k * SP + ia];
        float4 bb = *(const float4*)&Ys[k * SP + ja];
        float av[4] = {a.x, a.y, a.z, a.w};
        float bv[4] = {bb.x, bb.y, bb.z, bb.w};
#pragma unroll
        for (int r = 0; r < 4; ++r)
#pragma unroll
            for (int c = 0; c < 4; ++c)
                acc[r][c] = fmaf(av[r], bv[c], acc[r][c]);
    }

    float x2v[4], y2v[4];
#pragma unroll
    for (int r = 0; r < 4; ++r) x2v[r] = g_x2[b * N_ + i0 + ia + r];
#pragma unroll
    for (int c = 0; c < 4; ++c) y2v[c] = g_y2[b * M_ + j0 + ja + c];

    float* Db = g_D + ((size_t)b * N_ + (i0 + ia)) * M_ + j0 + ja;
#pragma unroll
    for (int r = 0; r < 4; ++r) {
        float4 o;
        o.x = fmaf(-2.f, acc[r][0], x2v[r] + y2v[0]);
        o.y = fmaf(-2.f, acc[r][1], x2v[r] + y2v[1]);
        o.z = fmaf(-2.f, acc[r][2], x2v[r] + y2v[2]);
        o.w = fmaf(-2.f, acc[r][3], x2v[r] + y2v[3]);
        *(float4*)(Db + r * M_) = o;
    }
}

// ---------------------------------------------------------------------------
// Kernel 3: soft-DTW anti-diagonal wavefront DP.
// One block per batch, thread tid handles row i = tid+1.
// Three rotating diagonal buffers in smem. D prefetched 2 diagonals ahead.
// ---------------------------------------------------------------------------
__global__ __launch_bounds__(512) void dtw_kernel(float* __restrict__ out) {
    __shared__ float buf[3][N_ + 1];
    const int b   = blockIdx.x;
    const int tid = threadIdx.x;               // i = tid + 1
    const float* Dp = g_D + (size_t)b * N_ * M_ + (size_t)tid * M_;

    // init: diag k=0 -> R[0,0]=0 else BIG; diag k=1 -> all BIG
    if (tid == 0) { buf[0][0] = 0.f; buf[1][0] = BIGF; buf[2][0] = BIGF; }
    buf[0][tid + 1] = BIGF;
    buf[1][tid + 1] = BIGF;
    __syncthreads();

    // j at diagonal k (for this thread) is j = k - tid - 1; cell valid iff 1<=j<=M_.
    // Prefetch distances for k=2 and k=3.
    float dcur = (tid == 0) ? Dp[0] : 0.f;     // k=2: only tid=0 valid (j=1)
    float dnxt = 0.f;
    {
        int jj = 3 - tid - 1;
        if (jj >= 1 && jj <= M_) dnxt = Dp[jj - 1];
    }

    const int KMAX = N_ + M_;                  // 1024
    for (int k = 2; k <= KMAX; ++k) {
        // prefetch distance for diagonal k+2 (two steps ahead -> hides L2 latency)
        float dpre = 0.f;
        int jp = k + 1 - tid;                  // j at diag k+2
        if (jp >= 1 && jp <= M_ && k + 2 <= KMAX) dpre = Dp[jp - 1];

        float* bk   = buf[k % 3];
        float* bkm1 = buf[(k + 2) % 3];        // == (k-1) % 3
        float* bkm2 = buf[(k + 1) % 3];        // == (k-2) % 3

        float r0 = bkm2[tid];                  // R[i-1, j-1]
        float r1 = bkm1[tid];                  // R[i-1, j]
        float r2 = bkm1[tid + 1];              // R[i,   j-1]

        float m = fminf(r0, fminf(r1, r2));
        float s = __expf(m - r0) + __expf(m - r1) + __expf(m - r2);
        float val = dcur + m - __logf(s);

        int j = k - tid - 1;
        bk[tid + 1] = (j >= 1 && j <= M_) ? val : BIGF;
        if (tid == 0) bk[0] = BIGF;            // R[0, j] = BIG for j >= 1
        __syncthreads();

        dcur = dnxt;
        dnxt = dpre;
    }

    // R[N, M] lives at buf[(N+M) % 3][N], written by tid = N_-1 (who reads it here)
    if (tid == N_ - 1) out[b] = buf[KMAX % 3][N_];
}

// ---------------------------------------------------------------------------
extern "C" void kernel_launch(void* const* d_in, const int* in_sizes, int n_in,
                              void* d_out, int out_size) {
    const float* x = (const float*)d_in[0];
    const float* y = (const float*)d_in[1];
    float* out = (float*)d_out;

    // 1) norms: 2 * 32 * 512 rows, one thread per row
    norm_kernel<<<(2 * B_ * N_) / 256, 256>>>(x, y);

    // 2) distance matrices: 8x8 tiles of 64x64 per batch
    dim3 dgrid(M_ / TS, N_ / TS, B_);
    dist_kernel<<<dgrid, 256>>>(x, y);

    // 3) wavefront DP: one block per batch
    dtw_kernel<<<B_, 512>>>(out);
}